// round 2
// baseline (speedup 1.0000x reference)
#include <cuda_runtime.h>
#include <math.h>

#define T_TOT 32768
#define DM    256
#define FFN   1024

// 128 MB scratch for fused[T, FFN] (allocation-free rule: __device__ global)
__device__ float g_fused[(size_t)T_TOT * FFN];

__device__ __forceinline__ float sigf(float z) {
    return 1.0f / (1.0f + __expf(-z));
}

// ---------------------------------------------------------------------------
// Kernel 1: fused[t, j] = g * trop + (1-g) * classical
//   trop      from max-plus over D plus convex/concave P=8 epilogue
//   classical = gelu(x@Wc + bc)
//   g         = sigmoid(x@Wg + bg)
// Tile: 64 (tokens) x 64 (ffn), K chunks of 32, 256 threads, 4x4 per thread.
// ---------------------------------------------------------------------------
__global__ __launch_bounds__(256) void dtn_fused_kernel(
    const float* __restrict__ x,       // [T, 256]
    const float* __restrict__ Wt,      // [1024, 256]
    const float* __restrict__ bt,      // [1024]
    const float* __restrict__ sl_cvx,  // [1024, 8]
    const float* __restrict__ of_cvx,  // [1024, 8]
    const float* __restrict__ sl_ccv,  // [1024, 8]
    const float* __restrict__ of_ccv,  // [1024, 8]
    const float* __restrict__ alpha,   // [1024]
    const float* __restrict__ Wc,      // [256, 1024]
    const float* __restrict__ bc,      // [1024]
    const float* __restrict__ Wg,      // [256, 1024]
    const float* __restrict__ bg)      // [1024]
{
    // k-major tiles; row stride 68 floats = 272B (16B-aligned, depadded banks)
    __shared__ float xs [32][68];
    __shared__ float wts[32][68];
    __shared__ float wcs[32][68];
    __shared__ float wgs[32][68];

    const int tid = threadIdx.x;
    const int tx  = tid & 15;   // ffn direction, 4 cols each
    const int ty  = tid >> 4;   // token direction, 4 rows each
    const int m0  = blockIdx.y * 64;
    const int n0  = blockIdx.x * 64;

    const float NEG_INF = __int_as_float(0xff800000);
    float tmax[4][4], accc[4][4], accg[4][4];
#pragma unroll
    for (int i = 0; i < 4; i++)
#pragma unroll
        for (int j = 0; j < 4; j++) {
            tmax[i][j] = NEG_INF; accc[i][j] = 0.0f; accg[i][j] = 0.0f;
        }

    for (int kc = 0; kc < DM; kc += 32) {
#pragma unroll
        for (int r = 0; r < 2; r++) {
            const int idx  = tid + r * 256;      // 0..511
            const int row  = idx >> 3;           // 0..63
            const int kq   = idx & 7;            // 0..7 (k quad)
            // x tile (transpose to k-major)
            float4 xv = *(const float4*)(x + (size_t)(m0 + row) * DM + kc + kq * 4);
            xs[kq*4+0][row] = xv.x; xs[kq*4+1][row] = xv.y;
            xs[kq*4+2][row] = xv.z; xs[kq*4+3][row] = xv.w;
            // Wt tile (j-major in gmem -> transpose to k-major)
            float4 wv = *(const float4*)(Wt + (size_t)(n0 + row) * DM + kc + kq * 4);
            wts[kq*4+0][row] = wv.x; wts[kq*4+1][row] = wv.y;
            wts[kq*4+2][row] = wv.z; wts[kq*4+3][row] = wv.w;
            // Wc / Wg tiles (already k-major)
            const int krow = idx >> 4;           // 0..31
            const int jq   = idx & 15;           // 0..15
            *(float4*)&wcs[krow][jq*4] =
                *(const float4*)(Wc + (size_t)(kc + krow) * FFN + n0 + jq * 4);
            *(float4*)&wgs[krow][jq*4] =
                *(const float4*)(Wg + (size_t)(kc + krow) * FFN + n0 + jq * 4);
        }
        __syncthreads();

#pragma unroll
        for (int kk = 0; kk < 32; kk++) {
            const float4 xa = *(const float4*)&xs [kk][ty * 4];
            const float4 wa = *(const float4*)&wts[kk][tx * 4];
            const float4 ca = *(const float4*)&wcs[kk][tx * 4];
            const float4 ga = *(const float4*)&wgs[kk][tx * 4];
            const float xm[4] = {xa.x, xa.y, xa.z, xa.w};
            const float wn[4] = {wa.x, wa.y, wa.z, wa.w};
            const float cn[4] = {ca.x, ca.y, ca.z, ca.w};
            const float gn[4] = {ga.x, ga.y, ga.z, ga.w};
#pragma unroll
            for (int mi = 0; mi < 4; mi++)
#pragma unroll
                for (int ni = 0; ni < 4; ni++) {
                    tmax[mi][ni] = fmaxf(tmax[mi][ni], xm[mi] + wn[ni]);
                    accc[mi][ni] = fmaf(xm[mi], cn[ni], accc[mi][ni]);
                    accg[mi][ni] = fmaf(xm[mi], gn[ni], accg[mi][ni]);
                }
        }
        __syncthreads();
    }

    // Epilogue
#pragma unroll
    for (int ni = 0; ni < 4; ni++) {
        const int j = n0 + tx * 4 + ni;
        const float btj = bt[j];
        const float s   = sigf(alpha[j]);
        const float bcj = bc[j];
        const float bgj = bg[j];
        const float4 sc0 = *(const float4*)(sl_cvx + (size_t)j * 8);
        const float4 sc1 = *(const float4*)(sl_cvx + (size_t)j * 8 + 4);
        const float4 oc0 = *(const float4*)(of_cvx + (size_t)j * 8);
        const float4 oc1 = *(const float4*)(of_cvx + (size_t)j * 8 + 4);
        const float4 sv0 = *(const float4*)(sl_ccv + (size_t)j * 8);
        const float4 sv1 = *(const float4*)(sl_ccv + (size_t)j * 8 + 4);
        const float4 ov0 = *(const float4*)(of_ccv + (size_t)j * 8);
        const float4 ov1 = *(const float4*)(of_ccv + (size_t)j * 8 + 4);
#pragma unroll
        for (int mi = 0; mi < 4; mi++) {
            const float t = tmax[mi][ni] + btj;
            float cvx = fmaf(t, sc0.x, oc0.x);
            cvx = fmaxf(cvx, fmaf(t, sc0.y, oc0.y));
            cvx = fmaxf(cvx, fmaf(t, sc0.z, oc0.z));
            cvx = fmaxf(cvx, fmaf(t, sc0.w, oc0.w));
            cvx = fmaxf(cvx, fmaf(t, sc1.x, oc1.x));
            cvx = fmaxf(cvx, fmaf(t, sc1.y, oc1.y));
            cvx = fmaxf(cvx, fmaf(t, sc1.z, oc1.z));
            cvx = fmaxf(cvx, fmaf(t, sc1.w, oc1.w));
            float ccv = fmaf(t, sv0.x, ov0.x);
            ccv = fminf(ccv, fmaf(t, sv0.y, ov0.y));
            ccv = fminf(ccv, fmaf(t, sv0.z, ov0.z));
            ccv = fminf(ccv, fmaf(t, sv0.w, ov0.w));
            ccv = fminf(ccv, fmaf(t, sv1.x, ov1.x));
            ccv = fminf(ccv, fmaf(t, sv1.y, ov1.y));
            ccv = fminf(ccv, fmaf(t, sv1.z, ov1.z));
            ccv = fminf(ccv, fmaf(t, sv1.w, ov1.w));
            const float trop = s * cvx + (1.0f - s) * ccv;

            const float v   = accc[mi][ni] + bcj;
            const float cls = 0.5f * v * (1.0f + erff(v * 0.70710678118654752f));
            const float g   = sigf(accg[mi][ni] + bgj);

            g_fused[(size_t)(m0 + ty * 4 + mi) * FFN + j] =
                g * trop + (1.0f - g) * cls;
        }
    }
}

// ---------------------------------------------------------------------------
// Kernel 2: out[T, 256] = fused[T, 1024] @ Wd[1024, 256] + bd
// Tile: 64 x 64, K chunks of 32, 256 threads, 4x4 per thread.
// ---------------------------------------------------------------------------
__global__ __launch_bounds__(256) void dtn_out_kernel(
    const float* __restrict__ Wd,      // [1024, 256]
    const float* __restrict__ bd,      // [256]
    float* __restrict__ out)           // [T, 256]
{
    __shared__ float fs [32][68];
    __shared__ float wds[32][68];

    const int tid = threadIdx.x;
    const int tx  = tid & 15;
    const int ty  = tid >> 4;
    const int m0  = blockIdx.y * 64;
    const int n0  = blockIdx.x * 64;

    float acc[4][4];
#pragma unroll
    for (int i = 0; i < 4; i++)
#pragma unroll
        for (int j = 0; j < 4; j++) acc[i][j] = 0.0f;

    for (int kc = 0; kc < FFN; kc += 32) {
#pragma unroll
        for (int r = 0; r < 2; r++) {
            const int idx  = tid + r * 256;
            const int row  = idx >> 3;
            const int kq   = idx & 7;
            float4 fv = *(const float4*)(g_fused + (size_t)(m0 + row) * FFN + kc + kq * 4);
            fs[kq*4+0][row] = fv.x; fs[kq*4+1][row] = fv.y;
            fs[kq*4+2][row] = fv.z; fs[kq*4+3][row] = fv.w;
            const int krow = idx >> 4;
            const int jq   = idx & 15;
            *(float4*)&wds[krow][jq*4] =
                *(const float4*)(Wd + (size_t)(kc + krow) * DM + n0 + jq * 4);
        }
        __syncthreads();

#pragma unroll
        for (int kk = 0; kk < 32; kk++) {
            const float4 fa = *(const float4*)&fs [kk][ty * 4];
            const float4 wa = *(const float4*)&wds[kk][tx * 4];
            const float fm[4] = {fa.x, fa.y, fa.z, fa.w};
            const float wn[4] = {wa.x, wa.y, wa.z, wa.w};
#pragma unroll
            for (int mi = 0; mi < 4; mi++)
#pragma unroll
                for (int ni = 0; ni < 4; ni++)
                    acc[mi][ni] = fmaf(fm[mi], wn[ni], acc[mi][ni]);
        }
        __syncthreads();
    }

    const float4 bdv = *(const float4*)(bd + n0 + tx * 4);
#pragma unroll
    for (int mi = 0; mi < 4; mi++) {
        float4 o;
        o.x = acc[mi][0] + bdv.x;
        o.y = acc[mi][1] + bdv.y;
        o.z = acc[mi][2] + bdv.z;
        o.w = acc[mi][3] + bdv.w;
        *(float4*)(out + (size_t)(m0 + ty * 4 + mi) * DM + n0 + tx * 4) = o;
    }
}

extern "C" void kernel_launch(void* const* d_in, const int* in_sizes, int n_in,
                              void* d_out, int out_size) {
    const float* x      = (const float*)d_in[0];
    const float* Wt     = (const float*)d_in[1];
    const float* bt     = (const float*)d_in[2];
    const float* sl_cvx = (const float*)d_in[3];
    const float* of_cvx = (const float*)d_in[4];
    const float* sl_ccv = (const float*)d_in[5];
    const float* of_ccv = (const float*)d_in[6];
    const float* alpha  = (const float*)d_in[7];
    const float* Wc     = (const float*)d_in[8];
    const float* bc     = (const float*)d_in[9];
    const float* Wg     = (const float*)d_in[10];
    const float* bg     = (const float*)d_in[11];
    const float* Wd     = (const float*)d_in[12];
    const float* bd     = (const float*)d_in[13];
    float* out = (float*)d_out;

    dim3 grid1(FFN / 64, T_TOT / 64);   // (16, 512)
    dtn_fused_kernel<<<grid1, 256>>>(x, Wt, bt, sl_cvx, of_cvx, sl_ccv, of_ccv,
                                     alpha, Wc, bc, Wg, bg);

    dim3 grid2(DM / 64, T_TOT / 64);    // (4, 512)
    dtn_out_kernel<<<grid2, 256>>>(Wd, bd, out);
}

// round 3
// speedup vs baseline: 1.1300x; 1.1300x over previous
#include <cuda_runtime.h>
#include <math.h>

#define T_TOT 32768
#define DM    256
#define FFN   1024

// 128 MB scratch for fused[T, FFN] (allocation-free rule: __device__ global)
__device__ float g_fused[(size_t)T_TOT * FFN];

__device__ __forceinline__ float sigf(float z) {
    return 1.0f / (1.0f + __expf(-z));
}

// ---- f32x2 packed-math helpers (sm_103a FFMA2 path) -----------------------
__device__ __forceinline__ unsigned long long pack2(float lo, float hi) {
    unsigned long long r;
    asm("mov.b64 %0, {%1, %2};" : "=l"(r) : "f"(lo), "f"(hi));
    return r;
}
__device__ __forceinline__ void unpack2(unsigned long long v, float& lo, float& hi) {
    asm("mov.b64 {%0, %1}, %2;" : "=f"(lo), "=f"(hi) : "l"(v));
}
__device__ __forceinline__ unsigned long long fma2(unsigned long long a,
                                                   unsigned long long b,
                                                   unsigned long long c) {
    unsigned long long d;
    asm("fma.rn.f32x2 %0, %1, %2, %3;" : "=l"(d) : "l"(a), "l"(b), "l"(c));
    return d;
}
__device__ __forceinline__ unsigned long long add2(unsigned long long a,
                                                   unsigned long long b) {
    unsigned long long d;
    asm("add.rn.f32x2 %0, %1, %2;" : "=l"(d) : "l"(a), "l"(b));
    return d;
}

// ---------------------------------------------------------------------------
// Kernel 1: fused[t, j] = g * trop + (1-g) * classical
// Block tile 128 (tokens) x 64 (ffn), K chunks of 16, 256 threads,
// per-thread 8m x 4n. FMA accumulators n-packed in f32x2 pairs.
// ---------------------------------------------------------------------------
__global__ __launch_bounds__(256) void dtn_fused_kernel(
    const float* __restrict__ x,       // [T, 256]
    const float* __restrict__ Wt,      // [1024, 256]
    const float* __restrict__ bt,      // [1024]
    const float* __restrict__ sl_cvx,  // [1024, 8]
    const float* __restrict__ of_cvx,  // [1024, 8]
    const float* __restrict__ sl_ccv,  // [1024, 8]
    const float* __restrict__ of_ccv,  // [1024, 8]
    const float* __restrict__ alpha,   // [1024]
    const float* __restrict__ Wc,      // [256, 1024]
    const float* __restrict__ bc,      // [1024]
    const float* __restrict__ Wg,      // [256, 1024]
    const float* __restrict__ bg)      // [1024]
{
    // k-major tiles; strides chosen: mult of 4 floats (LDS.128 align), low conflict
    __shared__ float xs [16][132];
    __shared__ float wts[16][68];
    __shared__ float wcs[16][68];
    __shared__ float wgs[16][68];

    const int tid = threadIdx.x;
    const int tx  = tid & 15;   // ffn dir, 4 cols each
    const int ty  = tid >> 4;   // token dir, 8 rows each
    const int m0  = blockIdx.y * 128;
    const int n0  = blockIdx.x * 64;

    const float NEG_INF = __int_as_float(0xff800000);
    float tmax[8][4];
    unsigned long long c2[8][2], g2[8][2];   // n-packed fp32 pairs
    const unsigned long long zz = 0ull;
#pragma unroll
    for (int i = 0; i < 8; i++) {
        c2[i][0] = zz; c2[i][1] = zz; g2[i][0] = zz; g2[i][1] = zz;
#pragma unroll
        for (int j = 0; j < 4; j++) tmax[i][j] = NEG_INF;
    }

    for (int kc = 0; kc < DM; kc += 16) {
        // --- x tile: 128 rows x 16 k, transpose to k-major (2 float4/thread)
#pragma unroll
        for (int r = 0; r < 2; r++) {
            const int idx = tid + r * 256;     // 0..511
            const int row = idx >> 2;          // 0..127
            const int kq  = idx & 3;           // 0..3
            float4 v = *(const float4*)(x + (size_t)(m0 + row) * DM + kc + kq * 4);
            xs[kq*4+0][row] = v.x; xs[kq*4+1][row] = v.y;
            xs[kq*4+2][row] = v.z; xs[kq*4+3][row] = v.w;
        }
        // --- Wt tile: 64 rows x 16 k, transpose (1 float4/thread)
        {
            const int row = tid >> 2;          // 0..63
            const int kq  = tid & 3;
            float4 v = *(const float4*)(Wt + (size_t)(n0 + row) * DM + kc + kq * 4);
            wts[kq*4+0][row] = v.x; wts[kq*4+1][row] = v.y;
            wts[kq*4+2][row] = v.z; wts[kq*4+3][row] = v.w;
        }
        // --- Wc / Wg tiles: k-major already (1 float4/thread each)
        {
            const int krow = tid >> 4;         // 0..15
            const int jq   = tid & 15;         // 0..15
            *(float4*)&wcs[krow][jq*4] =
                *(const float4*)(Wc + (size_t)(kc + krow) * FFN + n0 + jq * 4);
            *(float4*)&wgs[krow][jq*4] =
                *(const float4*)(Wg + (size_t)(kc + krow) * FFN + n0 + jq * 4);
        }
        __syncthreads();

#pragma unroll
        for (int kk = 0; kk < 16; kk++) {
            const float4 xa0 = *(const float4*)&xs[kk][ty * 8];
            const float4 xa1 = *(const float4*)&xs[kk][ty * 8 + 4];
            const float4 wa  = *(const float4*)&wts[kk][tx * 4];
            const float4 ca  = *(const float4*)&wcs[kk][tx * 4];
            const float4 ga  = *(const float4*)&wgs[kk][tx * 4];
            const float xm[8] = {xa0.x, xa0.y, xa0.z, xa0.w,
                                 xa1.x, xa1.y, xa1.z, xa1.w};
            // n-pairs: (n0,n1) and (n2,n3) — come straight from the float4 regs
            const unsigned long long wp[2] = {pack2(wa.x, wa.y), pack2(wa.z, wa.w)};
            const unsigned long long cp[2] = {pack2(ca.x, ca.y), pack2(ca.z, ca.w)};
            const unsigned long long gp[2] = {pack2(ga.x, ga.y), pack2(ga.z, ga.w)};
#pragma unroll
            for (int mi = 0; mi < 8; mi++) {
                const unsigned long long xd = pack2(xm[mi], xm[mi]);
#pragma unroll
                for (int p = 0; p < 2; p++) {
                    c2[mi][p] = fma2(xd, cp[p], c2[mi][p]);
                    g2[mi][p] = fma2(xd, gp[p], g2[mi][p]);
                    const unsigned long long t2 = add2(xd, wp[p]);
                    float tlo, thi;
                    unpack2(t2, tlo, thi);
                    tmax[mi][2*p+0] = fmaxf(tmax[mi][2*p+0], tlo);
                    tmax[mi][2*p+1] = fmaxf(tmax[mi][2*p+1], thi);
                }
            }
        }
        __syncthreads();
    }

    // Epilogue
#pragma unroll
    for (int ni = 0; ni < 4; ni++) {
        const int j = n0 + tx * 4 + ni;
        const float btj = bt[j];
        const float s   = sigf(alpha[j]);
        const float bcj = bc[j];
        const float bgj = bg[j];
        const float4 sc0 = *(const float4*)(sl_cvx + (size_t)j * 8);
        const float4 sc1 = *(const float4*)(sl_cvx + (size_t)j * 8 + 4);
        const float4 oc0 = *(const float4*)(of_cvx + (size_t)j * 8);
        const float4 oc1 = *(const float4*)(of_cvx + (size_t)j * 8 + 4);
        const float4 sv0 = *(const float4*)(sl_ccv + (size_t)j * 8);
        const float4 sv1 = *(const float4*)(sl_ccv + (size_t)j * 8 + 4);
        const float4 ov0 = *(const float4*)(of_ccv + (size_t)j * 8);
        const float4 ov1 = *(const float4*)(of_ccv + (size_t)j * 8 + 4);
#pragma unroll
        for (int mi = 0; mi < 8; mi++) {
            float clo, chi, glo, ghi;
            unpack2(c2[mi][ni >> 1], clo, chi);
            unpack2(g2[mi][ni >> 1], glo, ghi);
            const float accc = (ni & 1) ? chi : clo;
            const float accg = (ni & 1) ? ghi : glo;

            const float t = tmax[mi][ni] + btj;
            float cvx = fmaf(t, sc0.x, oc0.x);
            cvx = fmaxf(cvx, fmaf(t, sc0.y, oc0.y));
            cvx = fmaxf(cvx, fmaf(t, sc0.z, oc0.z));
            cvx = fmaxf(cvx, fmaf(t, sc0.w, oc0.w));
            cvx = fmaxf(cvx, fmaf(t, sc1.x, oc1.x));
            cvx = fmaxf(cvx, fmaf(t, sc1.y, oc1.y));
            cvx = fmaxf(cvx, fmaf(t, sc1.z, oc1.z));
            cvx = fmaxf(cvx, fmaf(t, sc1.w, oc1.w));
            float ccv = fmaf(t, sv0.x, ov0.x);
            ccv = fminf(ccv, fmaf(t, sv0.y, ov0.y));
            ccv = fminf(ccv, fmaf(t, sv0.z, ov0.z));
            ccv = fminf(ccv, fmaf(t, sv0.w, ov0.w));
            ccv = fminf(ccv, fmaf(t, sv1.x, ov1.x));
            ccv = fminf(ccv, fmaf(t, sv1.y, ov1.y));
            ccv = fminf(ccv, fmaf(t, sv1.z, ov1.z));
            ccv = fminf(ccv, fmaf(t, sv1.w, ov1.w));
            const float trop = s * cvx + (1.0f - s) * ccv;

            const float v   = accc + bcj;
            const float cls = 0.5f * v * (1.0f + erff(v * 0.70710678118654752f));
            const float g   = sigf(accg + bgj);

            g_fused[(size_t)(m0 + ty * 8 + mi) * FFN + j] =
                g * trop + (1.0f - g) * cls;
        }
    }
}

// ---------------------------------------------------------------------------
// Kernel 2: out[T, 256] = fused[T, 1024] @ Wd[1024, 256] + bd
// Block tile 128 x 64, K chunks of 16, 256 threads, per-thread 8m x 4n.
// FMA accumulators m-packed in f32x2 pairs (x pairs free from float4 loads).
// ---------------------------------------------------------------------------
__global__ __launch_bounds__(256) void dtn_out_kernel(
    const float* __restrict__ Wd,      // [1024, 256]
    const float* __restrict__ bd,      // [256]
    float* __restrict__ out)           // [T, 256]
{
    __shared__ float fs [16][132];
    __shared__ float wds[16][68];

    const int tid = threadIdx.x;
    const int tx  = tid & 15;   // n dir, 4 each
    const int ty  = tid >> 4;   // m dir, 8 each
    const int m0  = blockIdx.y * 128;
    const int n0  = blockIdx.x * 64;

    unsigned long long a2[4][4];   // m-packed pairs x 4 n
#pragma unroll
    for (int i = 0; i < 4; i++)
#pragma unroll
        for (int j = 0; j < 4; j++) a2[i][j] = 0ull;

    for (int kc = 0; kc < FFN; kc += 16) {
#pragma unroll
        for (int r = 0; r < 2; r++) {
            const int idx = tid + r * 256;
            const int row = idx >> 2;          // 0..127
            const int kq  = idx & 3;
            float4 v = *(const float4*)(g_fused + (size_t)(m0 + row) * FFN + kc + kq * 4);
            fs[kq*4+0][row] = v.x; fs[kq*4+1][row] = v.y;
            fs[kq*4+2][row] = v.z; fs[kq*4+3][row] = v.w;
        }
        {
            const int krow = tid >> 4;         // 0..15
            const int jq   = tid & 15;
            *(float4*)&wds[krow][jq*4] =
                *(const float4*)(Wd + (size_t)(kc + krow) * DM + n0 + jq * 4);
        }
        __syncthreads();

#pragma unroll
        for (int kk = 0; kk < 16; kk++) {
            const float4 fa0 = *(const float4*)&fs[kk][ty * 8];
            const float4 fa1 = *(const float4*)&fs[kk][ty * 8 + 4];
            const float4 wa  = *(const float4*)&wds[kk][tx * 4];
            const unsigned long long xp[4] = {
                pack2(fa0.x, fa0.y), pack2(fa0.z, fa0.w),
                pack2(fa1.x, fa1.y), pack2(fa1.z, fa1.w)};
            const float wn[4] = {wa.x, wa.y, wa.z, wa.w};
#pragma unroll
            for (int ni = 0; ni < 4; ni++) {
                const unsigned long long wd2 = pack2(wn[ni], wn[ni]);
#pragma unroll
                for (int mp = 0; mp < 4; mp++)
                    a2[mp][ni] = fma2(xp[mp], wd2, a2[mp][ni]);
            }
        }
        __syncthreads();
    }

    const float4 bdv = *(const float4*)(bd + n0 + tx * 4);
#pragma unroll
    for (int mp = 0; mp < 4; mp++) {
        float lo[4], hi[4];
#pragma unroll
        for (int ni = 0; ni < 4; ni++) unpack2(a2[mp][ni], lo[ni], hi[ni]);
        float4 o0, o1;
        o0.x = lo[0] + bdv.x; o0.y = lo[1] + bdv.y;
        o0.z = lo[2] + bdv.z; o0.w = lo[3] + bdv.w;
        o1.x = hi[0] + bdv.x; o1.y = hi[1] + bdv.y;
        o1.z = hi[2] + bdv.z; o1.w = hi[3] + bdv.w;
        *(float4*)(out + (size_t)(m0 + ty * 8 + mp * 2 + 0) * DM + n0 + tx * 4) = o0;
        *(float4*)(out + (size_t)(m0 + ty * 8 + mp * 2 + 1) * DM + n0 + tx * 4) = o1;
    }
}

extern "C" void kernel_launch(void* const* d_in, const int* in_sizes, int n_in,
                              void* d_out, int out_size) {
    const float* x      = (const float*)d_in[0];
    const float* Wt     = (const float*)d_in[1];
    const float* bt     = (const float*)d_in[2];
    const float* sl_cvx = (const float*)d_in[3];
    const float* of_cvx = (const float*)d_in[4];
    const float* sl_ccv = (const float*)d_in[5];
    const float* of_ccv = (const float*)d_in[6];
    const float* alpha  = (const float*)d_in[7];
    const float* Wc     = (const float*)d_in[8];
    const float* bc     = (const float*)d_in[9];
    const float* Wg     = (const float*)d_in[10];
    const float* bg     = (const float*)d_in[11];
    const float* Wd     = (const float*)d_in[12];
    const float* bd     = (const float*)d_in[13];
    float* out = (float*)d_out;

    dim3 grid1(FFN / 64, T_TOT / 128);   // (16, 256)
    dtn_fused_kernel<<<grid1, 256>>>(x, Wt, bt, sl_cvx, of_cvx, sl_ccv, of_ccv,
                                     alpha, Wc, bc, Wg, bg);

    dim3 grid2(DM / 64, T_TOT / 128);    // (4, 256)
    dtn_out_kernel<<<grid2, 256>>>(Wd, bd, out);
}